// round 5
// baseline (speedup 1.0000x reference)
#include <cuda_runtime.h>
#include <cuda_fp16.h>
#include <cstdint>

// out = x @ V @ diag(S) @ U^T + bias  via mma.sync m16n8k16 fp16 (f32 accum).
// GEMM1 (NT): Ts[8192,1024] = x(f32->h)[8192,4096] @ Vth[1024,4096]^T  (Ts fp16)
// GEMM2 (NT): out[8192,4096] = Ts[8192,1024] @ U(f32->h)[4096,1024]^T + bias
// f32 operands are converted to fp16 inside the GEMM loaders (no separate passes).

#define CTA_M 128
#define CTA_N 128
#define CTA_K 32

static constexpr int A_BLK = 528;   // one m16k16 fragment tile: 512B payload + pad
static constexpr int B_BLK = 272;   // one n8k16 fragment tile:  256B payload + pad
static constexpr int A_STAGE = 8 * 2 * A_BLK;    // 8448
static constexpr int B_STAGE = 16 * 2 * B_BLK;   // 8704
static constexpr int SMEM_TOTAL = 2 * (A_STAGE + B_STAGE);  // 34304

// Scratch (allocation-free rule: __device__ globals)
__device__ __align__(128) __half g_Vth[1024 * 4096];  // (V*S)^T fp16
__device__ __align__(128) __half g_Ts[8192 * 1024];   // intermediate fp16

__device__ __forceinline__ void mma_f16(float& d0, float& d1, float& d2, float& d3,
                                        uint32_t a0, uint32_t a1, uint32_t a2, uint32_t a3,
                                        uint32_t b0, uint32_t b1) {
    asm volatile(
        "mma.sync.aligned.m16n8k16.row.col.f32.f16.f16.f32 "
        "{%0,%1,%2,%3}, {%4,%5,%6,%7}, {%8,%9}, {%0,%1,%2,%3};"
        : "+f"(d0), "+f"(d1), "+f"(d2), "+f"(d3)
        : "r"(a0), "r"(a1), "r"(a2), "r"(a3), "r"(b0), "r"(b1));
}

__device__ __forceinline__ uint32_t h2pack(float a, float b) {
    __half2 h = __floats2half2_rn(a, b);
    return *reinterpret_cast<uint32_t*>(&h);
}

// ---------------- prep: Vt[n][k] = fp16(V[k][n] * S[n]) ----------------
__global__ void prep_vt_h(const float* __restrict__ V, const float* __restrict__ S,
                          __half* __restrict__ Vt) {
    __shared__ float t[32][33];
    int k0 = blockIdx.x * 32;
    int n0 = blockIdx.y * 32;
    int tx = threadIdx.x, ty = threadIdx.y;
    #pragma unroll
    for (int r = ty; r < 32; r += 8)
        t[r][tx] = V[(size_t)(k0 + r) * 1024 + n0 + tx];
    __syncthreads();
    #pragma unroll
    for (int r = ty; r < 32; r += 8) {
        int n = n0 + r, k = k0 + tx;
        Vt[(size_t)n * 4096 + k] = __float2half_rn(t[tx][r] * S[n]);
    }
}

// ---------------- main NT GEMM: C[M,N] = A[M,K] @ B[N,K]^T ----------------
// A_F32/B_F32: operand is f32 in gmem, converted to fp16 in the loader.
// EPI_HALF: C is fp16 (GEMM1 -> Ts); else f32 with +bias (GEMM2).
template <bool A_F32, bool B_F32, bool EPI_HALF>
__global__ __launch_bounds__(256, 2) void fp16_gemm_nt(
    const void* __restrict__ Ag, const void* __restrict__ Bg,
    const float* __restrict__ bias, void* __restrict__ Cv,
    int K, int lda, int ldb, int ldc)
{
    extern __shared__ char sm[];
    const int tid = threadIdx.x;
    const int bm = blockIdx.y * CTA_M;
    const int bn = blockIdx.x * CTA_N;

    // 8 warps as 2(m) x 4(n); warp tile 64x32
    const int wid = tid >> 5, lane = tid & 31;
    const int wm = wid >> 2, wn = wid & 3;

    // fp16 loader indices (uint4 = 8 halves; 2 per thread per operand)
    const int rowH = tid >> 2;            // 0..63, +64 per j
    const int c8 = (tid & 3) * 8;
    const int ktH = c8 >> 4;
    const int ccH = c8 & 15;
    // f32 loader indices (float4 = 4 floats; 4 per thread per operand)
    const int rowF = tid >> 3;            // 0..31, +32 per j
    const int c4 = (tid & 7) * 4;
    const int ktF = c4 >> 4;
    const int ccF = c4 & 15;

    auto As = [&](int p) { return p * A_STAGE; };
    auto Bs = [&](int p) { return 2 * A_STAGE + p * B_STAGE; };

    float4 vaf[4]; uint4 vah[2];
    float4 vbf[4]; uint4 vbh[2];

    auto ldg = [&](int tc) {
        const int k0 = tc * CTA_K;
        if constexpr (A_F32) {
            const float* A = (const float*)Ag;
            #pragma unroll
            for (int j = 0; j < 4; j++)
                vaf[j] = *reinterpret_cast<const float4*>(
                    A + (size_t)(bm + rowF + 32 * j) * lda + k0 + c4);
        } else {
            const __half* A = (const __half*)Ag;
            #pragma unroll
            for (int j = 0; j < 2; j++)
                vah[j] = *reinterpret_cast<const uint4*>(
                    A + (size_t)(bm + rowH + 64 * j) * lda + k0 + c8);
        }
        if constexpr (B_F32) {
            const float* B = (const float*)Bg;
            #pragma unroll
            for (int j = 0; j < 4; j++)
                vbf[j] = *reinterpret_cast<const float4*>(
                    B + (size_t)(bn + rowF + 32 * j) * ldb + k0 + c4);
        } else {
            const __half* B = (const __half*)Bg;
            #pragma unroll
            for (int j = 0; j < 2; j++)
                vbh[j] = *reinterpret_cast<const uint4*>(
                    B + (size_t)(bn + rowH + 64 * j) * ldb + k0 + c8);
        }
    };

    auto sts = [&](int p) {
        // ---- A ----
        if constexpr (A_F32) {
            const int rA = rowF & 15;
            const int regA = ((rA >> 3) & 1) | ((ccF >> 3) << 1);
            const int laneB = (rA & 7) * 4 + ((ccF >> 1) & 3);
            #pragma unroll
            for (int j = 0; j < 4; j++) {
                int mt = (rowF >> 4) + 2 * j;
                char* blk = sm + As(p) + (mt * 2 + ktF) * A_BLK;
                *reinterpret_cast<uint32_t*>(blk + laneB * 16 + regA * 4) =
                    h2pack(vaf[j].x, vaf[j].y);
                *reinterpret_cast<uint32_t*>(blk + (laneB + 1) * 16 + regA * 4) =
                    h2pack(vaf[j].z, vaf[j].w);
            }
        } else {
            const int rA = rowH & 15;
            const int regA = ((rA >> 3) & 1) | ((ccH >> 3) << 1);
            const int laneB = (rA & 7) * 4;
            #pragma unroll
            for (int j = 0; j < 2; j++) {
                int mt = (rowH >> 4) + 4 * j;
                char* blk = sm + As(p) + (mt * 2 + ktH) * A_BLK;
                const uint32_t* pv = &vah[j].x;
                #pragma unroll
                for (int e = 0; e < 4; e++)
                    *reinterpret_cast<uint32_t*>(blk + (laneB + e) * 16 + regA * 4) = pv[e];
            }
        }
        // ---- B ----
        if constexpr (B_F32) {
            const int rB = rowF & 7;
            const int regB = ccF >> 3;
            const int laneB = rB * 4 + ((ccF >> 1) & 3);
            #pragma unroll
            for (int j = 0; j < 4; j++) {
                int nt = (rowF >> 3) + 4 * j;
                char* blk = sm + Bs(p) + (nt * 2 + ktF) * B_BLK;
                *reinterpret_cast<uint32_t*>(blk + laneB * 8 + regB * 4) =
                    h2pack(vbf[j].x, vbf[j].y);
                *reinterpret_cast<uint32_t*>(blk + (laneB + 1) * 8 + regB * 4) =
                    h2pack(vbf[j].z, vbf[j].w);
            }
        } else {
            const int rB = rowH & 7;
            const int regB = ccH >> 3;
            const int laneB = rB * 4;
            #pragma unroll
            for (int j = 0; j < 2; j++) {
                int nt = (rowH >> 3) + 8 * j;
                char* blk = sm + Bs(p) + (nt * 2 + ktH) * B_BLK;
                const uint32_t* pv = &vbh[j].x;
                #pragma unroll
                for (int e = 0; e < 4; e++)
                    *reinterpret_cast<uint32_t*>(blk + (laneB + e) * 8 + regB * 4) = pv[e];
            }
        }
    };

    float acc[4][4][4];
    #pragma unroll
    for (int i = 0; i < 4; i++)
        #pragma unroll
        for (int j = 0; j < 4; j++)
            #pragma unroll
            for (int r = 0; r < 4; r++)
                acc[i][j][r] = 0.0f;

    const int T = K / CTA_K;
    ldg(0);
    sts(0);
    __syncthreads();

    for (int tc = 0; tc < T; ++tc) {
        const int p = tc & 1;
        if (tc + 1 < T) ldg(tc + 1);

        #pragma unroll
        for (int ks = 0; ks < 2; ks++) {
            uint4 af[4];
            uint2 bf[4];
            #pragma unroll
            for (int mt = 0; mt < 4; mt++)
                af[mt] = *reinterpret_cast<const uint4*>(
                    sm + As(p) + ((wm * 4 + mt) * 2 + ks) * A_BLK + lane * 16);
            #pragma unroll
            for (int nt = 0; nt < 4; nt++)
                bf[nt] = *reinterpret_cast<const uint2*>(
                    sm + Bs(p) + ((wn * 4 + nt) * 2 + ks) * B_BLK + lane * 8);
            #pragma unroll
            for (int mt = 0; mt < 4; mt++)
                #pragma unroll
                for (int nt = 0; nt < 4; nt++)
                    mma_f16(acc[mt][nt][0], acc[mt][nt][1], acc[mt][nt][2], acc[mt][nt][3],
                            af[mt].x, af[mt].y, af[mt].z, af[mt].w,
                            bf[nt].x, bf[nt].y);
        }

        if (tc + 1 < T) sts((tc + 1) & 1);
        __syncthreads();
    }

    // ---- epilogue ----
    const int g = lane >> 2, tig = lane & 3;
    #pragma unroll
    for (int mt = 0; mt < 4; mt++) {
        #pragma unroll
        for (int nt = 0; nt < 4; nt++) {
            int row = bm + wm * 64 + mt * 16 + g;
            int col = bn + wn * 32 + nt * 8 + tig * 2;
            if (EPI_HALF) {
                __half* C = (__half*)Cv;
                uint32_t h0 = h2pack(acc[mt][nt][0], acc[mt][nt][1]);
                uint32_t h1 = h2pack(acc[mt][nt][2], acc[mt][nt][3]);
                *reinterpret_cast<uint32_t*>(C + (size_t)row * ldc + col) = h0;
                *reinterpret_cast<uint32_t*>(C + (size_t)(row + 8) * ldc + col) = h1;
            } else {
                float* C = (float*)Cv;
                float2 b = *reinterpret_cast<const float2*>(bias + col);
                float2 v0 = make_float2(acc[mt][nt][0] + b.x, acc[mt][nt][1] + b.y);
                float2 v1 = make_float2(acc[mt][nt][2] + b.x, acc[mt][nt][3] + b.y);
                *reinterpret_cast<float2*>(C + (size_t)row * ldc + col) = v0;
                *reinterpret_cast<float2*>(C + (size_t)(row + 8) * ldc + col) = v1;
            }
        }
    }
}

extern "C" void kernel_launch(void* const* d_in, const int* in_sizes, int n_in,
                              void* d_out, int out_size)
{
    const float* x    = (const float*)d_in[0];   // [8192,4096]
    const float* U    = (const float*)d_in[1];   // [4096,1024]
    const float* S    = (const float*)d_in[2];   // [1024]
    const float* V    = (const float*)d_in[3];   // [4096,1024]
    const float* bias = (const float*)d_in[4];   // [4096]
    float* out = (float*)d_out;                  // [8192,4096]

    __half *Vth = nullptr, *Ts = nullptr;
    cudaGetSymbolAddress((void**)&Vth, g_Vth);
    cudaGetSymbolAddress((void**)&Ts, g_Ts);

    // prep: Vt = (V*S)^T fp16
    prep_vt_h<<<dim3(128, 32), dim3(32, 8)>>>(V, S, Vth);

    // GEMM1: Ts = x @ Vth^T   (A f32 fused cvt, B fp16, fp16 epilogue)
    fp16_gemm_nt<true, false, true><<<dim3(1024 / CTA_N, 8192 / CTA_M), 256, SMEM_TOTAL>>>(
        x, Vth, nullptr, Ts, 4096, 4096, 4096, 1024);

    // GEMM2: out = Ts @ U^T + bias   (A fp16, B f32 fused cvt, f32 epilogue)
    fp16_gemm_nt<false, true, false><<<dim3(4096 / CTA_N, 8192 / CTA_M), 256, SMEM_TOTAL>>>(
        Ts, U, bias, out, 1024, 1024, 1024, 4096);
}

// round 6
// speedup vs baseline: 1.2712x; 1.2712x over previous
#include <cuda_runtime.h>
#include <cuda_fp16.h>
#include <cstdint>

// out = x @ V @ diag(S) @ U^T + bias  via mma.sync m16n8k16 fp16 (f32 accum),
// cp.async 3-stage pipeline + ldmatrix, all operands pre-converted to fp16.
// GEMM1 (NT): Ts[8192,1024] = xh @ Vth^T   (fp16 epilogue)
// GEMM2 (NT): out[8192,4096] = Ts @ Uh^T + bias (f32 epilogue)

#define CTA_M 128
#define CTA_N 256
#define CTA_K 64
#define NSTAGES 3

static constexpr int A_BYTES = CTA_M * CTA_K * 2;          // 16384
static constexpr int B_BYTES = CTA_N * CTA_K * 2;          // 32768
static constexpr int STAGE_BYTES = A_BYTES + B_BYTES;      // 49152
static constexpr int SMEM_TOTAL = NSTAGES * STAGE_BYTES;   // 147456

// Scratch (allocation-free rule: __device__ globals)
__device__ __align__(128) __half g_xh[8192 * 4096];
__device__ __align__(128) __half g_Vth[1024 * 4096];
__device__ __align__(128) __half g_Uh[4096 * 1024];
__device__ __align__(128) __half g_Ts[8192 * 1024];

__device__ __forceinline__ uint32_t smem_u32(const void* p) {
    uint32_t a;
    asm("{ .reg .u64 t; cvta.to.shared.u64 t, %1; cvt.u32.u64 %0, t; }" : "=r"(a) : "l"(p));
    return a;
}

__device__ __forceinline__ void cp16(uint32_t dst, const void* src) {
    asm volatile("cp.async.cg.shared.global [%0], [%1], 16;" :: "r"(dst), "l"(src));
}
__device__ __forceinline__ void cp_commit() {
    asm volatile("cp.async.commit_group;" ::: "memory");
}
template <int N>
__device__ __forceinline__ void cp_wait() {
    asm volatile("cp.async.wait_group %0;" :: "n"(N) : "memory");
}

__device__ __forceinline__ void ldsm4(uint32_t* r, uint32_t addr) {
    asm volatile("ldmatrix.sync.aligned.m8n8.x4.shared.b16 {%0,%1,%2,%3}, [%4];"
                 : "=r"(r[0]), "=r"(r[1]), "=r"(r[2]), "=r"(r[3]) : "r"(addr));
}

__device__ __forceinline__ void mma_f16(float* d,
                                        const uint32_t* a, uint32_t b0, uint32_t b1) {
    asm volatile(
        "mma.sync.aligned.m16n8k16.row.col.f32.f16.f16.f32 "
        "{%0,%1,%2,%3}, {%4,%5,%6,%7}, {%8,%9}, {%0,%1,%2,%3};"
        : "+f"(d[0]), "+f"(d[1]), "+f"(d[2]), "+f"(d[3])
        : "r"(a[0]), "r"(a[1]), "r"(a[2]), "r"(a[3]), "r"(b0), "r"(b1));
}

__device__ __forceinline__ uint32_t h2pack(float a, float b) {
    __half2 h = __floats2half2_rn(a, b);
    return *reinterpret_cast<uint32_t*>(&h);
}

// smem tile addressing: row-major, 128B (8 chunks of 16B) per row, XOR-8 swizzle.
__device__ __forceinline__ uint32_t tile_addr(uint32_t base, int row, int chunk) {
    return base + row * 128 + ((chunk ^ (row & 7)) << 4);
}
// ldmatrix lane address for a 16x16 frag tile at (base_row, kt)
__device__ __forceinline__ uint32_t frag_addr(uint32_t base, int base_row, int kt, int lane) {
    int r = base_row + (lane & 15);
    int chunk = kt * 2 + (lane >> 4);
    return tile_addr(base, r, chunk);
}

// ---------------- prep kernels ----------------
__global__ void cvt_f2h(const float* __restrict__ in, __half* __restrict__ out) {
    size_t i = (size_t)blockIdx.x * blockDim.x + threadIdx.x;
    float4 v = *reinterpret_cast<const float4*>(in + i * 4);
    __half2 h0 = __floats2half2_rn(v.x, v.y);
    __half2 h1 = __floats2half2_rn(v.z, v.w);
    *reinterpret_cast<uint2*>(out + i * 4) =
        make_uint2(*(uint32_t*)&h0, *(uint32_t*)&h1);
}

__global__ void prep_vt_h(const float* __restrict__ V, const float* __restrict__ S,
                          __half* __restrict__ Vt) {
    __shared__ float t[32][33];
    int k0 = blockIdx.x * 32;
    int n0 = blockIdx.y * 32;
    int tx = threadIdx.x, ty = threadIdx.y;
    #pragma unroll
    for (int r = ty; r < 32; r += 8)
        t[r][tx] = V[(size_t)(k0 + r) * 1024 + n0 + tx];
    __syncthreads();
    #pragma unroll
    for (int r = ty; r < 32; r += 8) {
        int n = n0 + r, k = k0 + tx;
        Vt[(size_t)n * 4096 + k] = __float2half_rn(t[tx][r] * S[n]);
    }
}

// ---------------- main NT GEMM: C[M,N] = A[M,K] @ B[N,K]^T ----------------
template <bool EPI_HALF>
__global__ __launch_bounds__(256, 1) void hgemm_async(
    const __half* __restrict__ A, const __half* __restrict__ B,
    const float* __restrict__ bias, void* __restrict__ Cv,
    int K, int lda, int ldb, int ldc)
{
    extern __shared__ char sm[];
    const uint32_t sbase = smem_u32(sm);
    const int tid = threadIdx.x;
    const int lane = tid & 31, wid = tid >> 5;
    const int wm = wid >> 2, wn = wid & 3;        // 2 x 4 warps, warp tile 64x64
    const int bm = blockIdx.y * CTA_M;
    const int bn = blockIdx.x * CTA_N;

    // loader: each thread copies chunk id = tid + 256*j ; row = id>>3, chunk = id&7
    const int lrow = tid >> 3;      // 0..31
    const int lc = tid & 7;

    auto load_stage = [&](int s, int k0) {
        uint32_t sa = sbase + s * STAGE_BYTES;
        uint32_t sb = sa + A_BYTES;
        const __half* gA = A + (size_t)bm * lda + k0 + lc * 8;
        const __half* gB = B + (size_t)bn * ldb + k0 + lc * 8;
        #pragma unroll
        for (int j = 0; j < 4; j++) {
            int r = lrow + 32 * j;
            cp16(tile_addr(sa, r, lc), gA + (size_t)r * lda);
        }
        #pragma unroll
        for (int j = 0; j < 8; j++) {
            int r = lrow + 32 * j;
            cp16(tile_addr(sb, r, lc), gB + (size_t)r * ldb);
        }
    };

    float acc[4][8][4];
    #pragma unroll
    for (int i = 0; i < 4; i++)
        #pragma unroll
        for (int j = 0; j < 8; j++)
            #pragma unroll
            for (int r = 0; r < 4; r++)
                acc[i][j][r] = 0.0f;

    const int T = K / CTA_K;
    load_stage(0, 0);
    cp_commit();
    load_stage(1, CTA_K);
    cp_commit();

    for (int it = 0; it < T; ++it) {
        cp_wait<1>();
        __syncthreads();
        if (it + 2 < T) load_stage((it + 2) % NSTAGES, (it + 2) * CTA_K);
        cp_commit();

        const int s = it % NSTAGES;
        const uint32_t sa = sbase + s * STAGE_BYTES;
        const uint32_t sb = sa + A_BYTES;

        #pragma unroll
        for (int kt = 0; kt < 4; kt++) {
            uint32_t af[4][4];
            uint32_t bf[4][4];
            #pragma unroll
            for (int mt = 0; mt < 4; mt++)
                ldsm4(af[mt], frag_addr(sa, wm * 64 + mt * 16, kt, lane));
            #pragma unroll
            for (int ng = 0; ng < 4; ng++)
                ldsm4(bf[ng], frag_addr(sb, wn * 64 + ng * 16, kt, lane));
            #pragma unroll
            for (int mt = 0; mt < 4; mt++) {
                #pragma unroll
                for (int ng = 0; ng < 4; ng++) {
                    mma_f16(acc[mt][2 * ng],     af[mt], bf[ng][0], bf[ng][2]);
                    mma_f16(acc[mt][2 * ng + 1], af[mt], bf[ng][1], bf[ng][3]);
                }
            }
        }
    }

    // ---- epilogue ----
    const int g = lane >> 2, tig = lane & 3;
    #pragma unroll
    for (int mt = 0; mt < 4; mt++) {
        #pragma unroll
        for (int nt = 0; nt < 8; nt++) {
            int row = bm + wm * 64 + mt * 16 + g;
            int col = bn + wn * 64 + nt * 8 + tig * 2;
            if (EPI_HALF) {
                __half* C = (__half*)Cv;
                *reinterpret_cast<uint32_t*>(C + (size_t)row * ldc + col) =
                    h2pack(acc[mt][nt][0], acc[mt][nt][1]);
                *reinterpret_cast<uint32_t*>(C + (size_t)(row + 8) * ldc + col) =
                    h2pack(acc[mt][nt][2], acc[mt][nt][3]);
            } else {
                float* C = (float*)Cv;
                float2 b = *reinterpret_cast<const float2*>(bias + col);
                *reinterpret_cast<float2*>(C + (size_t)row * ldc + col) =
                    make_float2(acc[mt][nt][0] + b.x, acc[mt][nt][1] + b.y);
                *reinterpret_cast<float2*>(C + (size_t)(row + 8) * ldc + col) =
                    make_float2(acc[mt][nt][2] + b.x, acc[mt][nt][3] + b.y);
            }
        }
    }
}

extern "C" void kernel_launch(void* const* d_in, const int* in_sizes, int n_in,
                              void* d_out, int out_size)
{
    const float* x    = (const float*)d_in[0];   // [8192,4096]
    const float* U    = (const float*)d_in[1];   // [4096,1024]
    const float* S    = (const float*)d_in[2];   // [1024]
    const float* V    = (const float*)d_in[3];   // [4096,1024]
    const float* bias = (const float*)d_in[4];   // [4096]
    float* out = (float*)d_out;                  // [8192,4096]

    __half *xh, *Vth, *Uh, *Ts;
    cudaGetSymbolAddress((void**)&xh, g_xh);
    cudaGetSymbolAddress((void**)&Vth, g_Vth);
    cudaGetSymbolAddress((void**)&Uh, g_Uh);
    cudaGetSymbolAddress((void**)&Ts, g_Ts);

    cudaFuncSetAttribute(hgemm_async<true>,
                         cudaFuncAttributeMaxDynamicSharedMemorySize, SMEM_TOTAL);
    cudaFuncSetAttribute(hgemm_async<false>,
                         cudaFuncAttributeMaxDynamicSharedMemorySize, SMEM_TOTAL);

    // prep
    cvt_f2h<<<(8192 * 4096 / 4) / 256, 256>>>(x, xh);
    cvt_f2h<<<(4096 * 1024 / 4) / 256, 256>>>(U, Uh);
    prep_vt_h<<<dim3(128, 32), dim3(32, 8)>>>(V, S, Vth);

    // GEMM1: Ts = xh @ Vth^T   (M=8192,N=1024,K=4096)
    hgemm_async<true><<<dim3(1024 / CTA_N, 8192 / CTA_M), 256, SMEM_TOTAL>>>(
        xh, Vth, nullptr, Ts, 4096, 4096, 4096, 1024);

    // GEMM2: out = Ts @ Uh^T + bias   (M=8192,N=4096,K=1024)
    hgemm_async<false><<<dim3(4096 / CTA_N, 8192 / CTA_M), 256, SMEM_TOTAL>>>(
        Ts, Uh, bias, out, 1024, 1024, 1024, 4096);
}

// round 7
// speedup vs baseline: 1.2715x; 1.0003x over previous
#include <cuda_runtime.h>
#include <cuda_fp16.h>
#include <cstdint>

// out = x @ V @ diag(S) @ U^T + bias  via mma.sync m16n8k16 fp16 (f32 accum),
// cp.async 3-stage pipeline + ldmatrix with register double-buffered fragments.
// GEMM1 (NT): Ts[8192,1024] = xh @ Vth^T   (fp16 epilogue)
// GEMM2 (NT): out[8192,4096] = Ts @ Uh^T + bias (f32 epilogue)

#define CTA_M 128
#define CTA_N 256
#define CTA_K 64
#define NSTAGES 3

static constexpr int A_BYTES = CTA_M * CTA_K * 2;          // 16384
static constexpr int B_BYTES = CTA_N * CTA_K * 2;          // 32768
static constexpr int STAGE_BYTES = A_BYTES + B_BYTES;      // 49152
static constexpr int SMEM_TOTAL = NSTAGES * STAGE_BYTES;   // 147456

// Scratch (allocation-free rule: __device__ globals)
__device__ __align__(128) __half g_xh[8192 * 4096];
__device__ __align__(128) __half g_Vth[1024 * 4096];
__device__ __align__(128) __half g_Uh[4096 * 1024];
__device__ __align__(128) __half g_Ts[8192 * 1024];

__device__ __forceinline__ uint32_t smem_u32(const void* p) {
    uint32_t a;
    asm("{ .reg .u64 t; cvta.to.shared.u64 t, %1; cvt.u32.u64 %0, t; }" : "=r"(a) : "l"(p));
    return a;
}

__device__ __forceinline__ void cp16(uint32_t dst, const void* src) {
    asm volatile("cp.async.cg.shared.global [%0], [%1], 16;" :: "r"(dst), "l"(src));
}
__device__ __forceinline__ void cp_commit() {
    asm volatile("cp.async.commit_group;" ::: "memory");
}
template <int N>
__device__ __forceinline__ void cp_wait() {
    asm volatile("cp.async.wait_group %0;" :: "n"(N) : "memory");
}

__device__ __forceinline__ void ldsm4(uint32_t* r, uint32_t addr) {
    asm volatile("ldmatrix.sync.aligned.m8n8.x4.shared.b16 {%0,%1,%2,%3}, [%4];"
                 : "=r"(r[0]), "=r"(r[1]), "=r"(r[2]), "=r"(r[3]) : "r"(addr));
}

__device__ __forceinline__ void mma_f16(float* d,
                                        const uint32_t* a, uint32_t b0, uint32_t b1) {
    asm volatile(
        "mma.sync.aligned.m16n8k16.row.col.f32.f16.f16.f32 "
        "{%0,%1,%2,%3}, {%4,%5,%6,%7}, {%8,%9}, {%0,%1,%2,%3};"
        : "+f"(d[0]), "+f"(d[1]), "+f"(d[2]), "+f"(d[3])
        : "r"(a[0]), "r"(a[1]), "r"(a[2]), "r"(a[3]), "r"(b0), "r"(b1));
}

__device__ __forceinline__ uint32_t h2pack(float a, float b) {
    __half2 h = __floats2half2_rn(a, b);
    return *reinterpret_cast<uint32_t*>(&h);
}

// smem tile addressing: 128B (8 x 16B chunks) per row, XOR-8 swizzle.
__device__ __forceinline__ uint32_t tile_addr(uint32_t base, int row, int chunk) {
    return base + row * 128 + ((chunk ^ (row & 7)) << 4);
}
__device__ __forceinline__ uint32_t frag_addr(uint32_t base, int base_row, int kt, int lane) {
    int r = base_row + (lane & 15);
    int chunk = kt * 2 + (lane >> 4);
    return tile_addr(base, r, chunk);
}

// ---------------- prep kernels ----------------
__global__ void cvt_f2h(const float* __restrict__ in, __half* __restrict__ out) {
    size_t i = (size_t)blockIdx.x * blockDim.x + threadIdx.x;
    float4 v = *reinterpret_cast<const float4*>(in + i * 4);
    __half2 h0 = __floats2half2_rn(v.x, v.y);
    __half2 h1 = __floats2half2_rn(v.z, v.w);
    *reinterpret_cast<uint2*>(out + i * 4) =
        make_uint2(*(uint32_t*)&h0, *(uint32_t*)&h1);
}

__global__ void prep_vt_h(const float* __restrict__ V, const float* __restrict__ S,
                          __half* __restrict__ Vt) {
    __shared__ float t[32][33];
    int k0 = blockIdx.x * 32;
    int n0 = blockIdx.y * 32;
    int tx = threadIdx.x, ty = threadIdx.y;
    #pragma unroll
    for (int r = ty; r < 32; r += 8)
        t[r][tx] = V[(size_t)(k0 + r) * 1024 + n0 + tx];
    __syncthreads();
    #pragma unroll
    for (int r = ty; r < 32; r += 8) {
        int n = n0 + r, k = k0 + tx;
        Vt[(size_t)n * 4096 + k] = __float2half_rn(t[tx][r] * S[n]);
    }
}

// ---------------- main NT GEMM: C[M,N] = A[M,K] @ B[N,K]^T ----------------
template <bool EPI_HALF>
__global__ __launch_bounds__(256, 1) void hgemm_async(
    const __half* __restrict__ A, const __half* __restrict__ B,
    const float* __restrict__ bias, void* __restrict__ Cv,
    int K, int lda, int ldb, int ldc)
{
    extern __shared__ char sm[];
    const uint32_t sbase = smem_u32(sm);
    const int tid = threadIdx.x;
    const int lane = tid & 31, wid = tid >> 5;
    const int wm = wid >> 2, wn = wid & 3;        // 2 x 4 warps, warp tile 64x64
    const int bm = blockIdx.y * CTA_M;
    const int bn = blockIdx.x * CTA_N;

    const int lrow = tid >> 3;      // 0..31
    const int lc = tid & 7;

    auto load_stage = [&](int s, int k0) {
        uint32_t sa = sbase + s * STAGE_BYTES;
        uint32_t sb = sa + A_BYTES;
        const __half* gA = A + (size_t)bm * lda + k0 + lc * 8;
        const __half* gB = B + (size_t)bn * ldb + k0 + lc * 8;
        #pragma unroll
        for (int j = 0; j < 4; j++) {
            int r = lrow + 32 * j;
            cp16(tile_addr(sa, r, lc), gA + (size_t)r * lda);
        }
        #pragma unroll
        for (int j = 0; j < 8; j++) {
            int r = lrow + 32 * j;
            cp16(tile_addr(sb, r, lc), gB + (size_t)r * ldb);
        }
    };

    float acc[4][8][4];
    #pragma unroll
    for (int i = 0; i < 4; i++)
        #pragma unroll
        for (int j = 0; j < 8; j++)
            #pragma unroll
            for (int r = 0; r < 4; r++)
                acc[i][j][r] = 0.0f;

    const int T = K / CTA_K;
    load_stage(0, 0);
    cp_commit();
    load_stage(1, CTA_K);
    cp_commit();

    uint32_t af[2][4][4];
    uint32_t bf[2][4][4];

    for (int it = 0; it < T; ++it) {
        cp_wait<1>();
        __syncthreads();
        if (it + 2 < T) load_stage((it + 2) % NSTAGES, (it + 2) * CTA_K);
        cp_commit();

        const int s = it % NSTAGES;
        const uint32_t sa = sbase + s * STAGE_BYTES;
        const uint32_t sb = sa + A_BYTES;

        // prefetch kt=0 fragments into buffer 0
        #pragma unroll
        for (int mt = 0; mt < 4; mt++)
            ldsm4(af[0][mt], frag_addr(sa, wm * 64 + mt * 16, 0, lane));
        #pragma unroll
        for (int ng = 0; ng < 4; ng++)
            ldsm4(bf[0][ng], frag_addr(sb, wn * 64 + ng * 16, 0, lane));

        #pragma unroll
        for (int kt = 0; kt < 4; kt++) {
            const int cur = kt & 1, nxt = cur ^ 1;
            if (kt < 3) {
                #pragma unroll
                for (int mt = 0; mt < 4; mt++)
                    ldsm4(af[nxt][mt], frag_addr(sa, wm * 64 + mt * 16, kt + 1, lane));
                #pragma unroll
                for (int ng = 0; ng < 4; ng++)
                    ldsm4(bf[nxt][ng], frag_addr(sb, wn * 64 + ng * 16, kt + 1, lane));
            }
            #pragma unroll
            for (int mt = 0; mt < 4; mt++) {
                #pragma unroll
                for (int ng = 0; ng < 4; ng++) {
                    mma_f16(acc[mt][2 * ng],     af[cur][mt], bf[cur][ng][0], bf[cur][ng][2]);
                    mma_f16(acc[mt][2 * ng + 1], af[cur][mt], bf[cur][ng][1], bf[cur][ng][3]);
                }
            }
        }
    }

    // ---- epilogue ----
    const int g = lane >> 2, tig = lane & 3;
    #pragma unroll
    for (int mt = 0; mt < 4; mt++) {
        #pragma unroll
        for (int nt = 0; nt < 8; nt++) {
            int row = bm + wm * 64 + mt * 16 + g;
            int col = bn + wn * 64 + nt * 8 + tig * 2;
            if (EPI_HALF) {
                __half* C = (__half*)Cv;
                *reinterpret_cast<uint32_t*>(C + (size_t)row * ldc + col) =
                    h2pack(acc[mt][nt][0], acc[mt][nt][1]);
                *reinterpret_cast<uint32_t*>(C + (size_t)(row + 8) * ldc + col) =
                    h2pack(acc[mt][nt][2], acc[mt][nt][3]);
            } else {
                float* C = (float*)Cv;
                float2 b = *reinterpret_cast<const float2*>(bias + col);
                *reinterpret_cast<float2*>(C + (size_t)row * ldc + col) =
                    make_float2(acc[mt][nt][0] + b.x, acc[mt][nt][1] + b.y);
                *reinterpret_cast<float2*>(C + (size_t)(row + 8) * ldc + col) =
                    make_float2(acc[mt][nt][2] + b.x, acc[mt][nt][3] + b.y);
            }
        }
    }
}

extern "C" void kernel_launch(void* const* d_in, const int* in_sizes, int n_in,
                              void* d_out, int out_size)
{
    const float* x    = (const float*)d_in[0];   // [8192,4096]
    const float* U    = (const float*)d_in[1];   // [4096,1024]
    const float* S    = (const float*)d_in[2];   // [1024]
    const float* V    = (const float*)d_in[3];   // [4096,1024]
    const float* bias = (const float*)d_in[4];   // [4096]
    float* out = (float*)d_out;                  // [8192,4096]

    __half *xh, *Vth, *Uh, *Ts;
    cudaGetSymbolAddress((void**)&xh, g_xh);
    cudaGetSymbolAddress((void**)&Vth, g_Vth);
    cudaGetSymbolAddress((void**)&Uh, g_Uh);
    cudaGetSymbolAddress((void**)&Ts, g_Ts);

    cudaFuncSetAttribute(hgemm_async<true>,
                         cudaFuncAttributeMaxDynamicSharedMemorySize, SMEM_TOTAL);
    cudaFuncSetAttribute(hgemm_async<false>,
                         cudaFuncAttributeMaxDynamicSharedMemorySize, SMEM_TOTAL);

    // prep
    cvt_f2h<<<(8192 * 4096 / 4) / 256, 256>>>(x, xh);
    cvt_f2h<<<(4096 * 1024 / 4) / 256, 256>>>(U, Uh);
    prep_vt_h<<<dim3(128, 32), dim3(32, 8)>>>(V, S, Vth);

    // GEMM1: Ts = xh @ Vth^T   (M=8192,N=1024,K=4096)
    hgemm_async<true><<<dim3(1024 / CTA_N, 8192 / CTA_M), 256, SMEM_TOTAL>>>(
        xh, Vth, nullptr, Ts, 4096, 4096, 4096, 1024);

    // GEMM2: out = Ts @ Uh^T + bias   (M=8192,N=4096,K=1024)
    hgemm_async<false><<<dim3(4096 / CTA_N, 8192 / CTA_M), 256, SMEM_TOTAL>>>(
        Ts, Uh, bias, out, 1024, 1024, 1024, 4096);
}

// round 8
// speedup vs baseline: 1.3176x; 1.0362x over previous
#include <cuda_runtime.h>
#include <cuda_fp16.h>
#include <cstdint>

// out = x @ V @ diag(S) @ U^T + bias  via mma.sync m16n8k16 fp16 (f32 accum),
// cp.async 3-stage pipeline + ldmatrix; CTA 128x128 so 2 CTAs/SM (16 warps).
// GEMM1 (NT): Ts[8192,1024] = xh @ Vth^T   (fp16 epilogue)
// GEMM2 (NT): out[8192,4096] = Ts @ Uh^T + bias (f32 epilogue)

#define CTA_M 128
#define CTA_N 128
#define CTA_K 64
#define NSTAGES 3

static constexpr int A_BYTES = CTA_M * CTA_K * 2;          // 16384
static constexpr int B_BYTES = CTA_N * CTA_K * 2;          // 16384
static constexpr int STAGE_BYTES = A_BYTES + B_BYTES;      // 32768
static constexpr int SMEM_TOTAL = NSTAGES * STAGE_BYTES;   // 98304

// Scratch (allocation-free rule: __device__ globals)
__device__ __align__(128) __half g_xh[8192 * 4096];
__device__ __align__(128) __half g_Vth[1024 * 4096];
__device__ __align__(128) __half g_Uh[4096 * 1024];
__device__ __align__(128) __half g_Ts[8192 * 1024];

__device__ __forceinline__ uint32_t smem_u32(const void* p) {
    uint32_t a;
    asm("{ .reg .u64 t; cvta.to.shared.u64 t, %1; cvt.u32.u64 %0, t; }" : "=r"(a) : "l"(p));
    return a;
}

__device__ __forceinline__ void cp16(uint32_t dst, const void* src) {
    asm volatile("cp.async.cg.shared.global [%0], [%1], 16;" :: "r"(dst), "l"(src));
}
__device__ __forceinline__ void cp_commit() {
    asm volatile("cp.async.commit_group;" ::: "memory");
}
template <int N>
__device__ __forceinline__ void cp_wait() {
    asm volatile("cp.async.wait_group %0;" :: "n"(N) : "memory");
}

__device__ __forceinline__ void ldsm4(uint32_t* r, uint32_t addr) {
    asm volatile("ldmatrix.sync.aligned.m8n8.x4.shared.b16 {%0,%1,%2,%3}, [%4];"
                 : "=r"(r[0]), "=r"(r[1]), "=r"(r[2]), "=r"(r[3]) : "r"(addr));
}

__device__ __forceinline__ void mma_f16(float* d,
                                        const uint32_t* a, uint32_t b0, uint32_t b1) {
    asm volatile(
        "mma.sync.aligned.m16n8k16.row.col.f32.f16.f16.f32 "
        "{%0,%1,%2,%3}, {%4,%5,%6,%7}, {%8,%9}, {%0,%1,%2,%3};"
        : "+f"(d[0]), "+f"(d[1]), "+f"(d[2]), "+f"(d[3])
        : "r"(a[0]), "r"(a[1]), "r"(a[2]), "r"(a[3]), "r"(b0), "r"(b1));
}

__device__ __forceinline__ uint32_t h2pack(float a, float b) {
    __half2 h = __floats2half2_rn(a, b);
    return *reinterpret_cast<uint32_t*>(&h);
}

// smem tile addressing: 128B (8 x 16B chunks) per row, XOR-8 swizzle.
__device__ __forceinline__ uint32_t tile_addr(uint32_t base, int row, int chunk) {
    return base + row * 128 + ((chunk ^ (row & 7)) << 4);
}
__device__ __forceinline__ uint32_t frag_addr(uint32_t base, int base_row, int kt, int lane) {
    int r = base_row + (lane & 15);
    int chunk = kt * 2 + (lane >> 4);
    return tile_addr(base, r, chunk);
}

// ---------------- prep kernels ----------------
__global__ void cvt_f2h(const float* __restrict__ in, __half* __restrict__ out) {
    size_t i = (size_t)blockIdx.x * blockDim.x + threadIdx.x;
    float4 v = *reinterpret_cast<const float4*>(in + i * 4);
    __half2 h0 = __floats2half2_rn(v.x, v.y);
    __half2 h1 = __floats2half2_rn(v.z, v.w);
    *reinterpret_cast<uint2*>(out + i * 4) =
        make_uint2(*(uint32_t*)&h0, *(uint32_t*)&h1);
}

__global__ void prep_vt_h(const float* __restrict__ V, const float* __restrict__ S,
                          __half* __restrict__ Vt) {
    __shared__ float t[32][33];
    int k0 = blockIdx.x * 32;
    int n0 = blockIdx.y * 32;
    int tx = threadIdx.x, ty = threadIdx.y;
    #pragma unroll
    for (int r = ty; r < 32; r += 8)
        t[r][tx] = V[(size_t)(k0 + r) * 1024 + n0 + tx];
    __syncthreads();
    #pragma unroll
    for (int r = ty; r < 32; r += 8) {
        int n = n0 + r, k = k0 + tx;
        Vt[(size_t)n * 4096 + k] = __float2half_rn(t[tx][r] * S[n]);
    }
}

// ---------------- main NT GEMM: C[M,N] = A[M,K] @ B[N,K]^T ----------------
template <bool EPI_HALF>
__global__ __launch_bounds__(256, 2) void hgemm_async(
    const __half* __restrict__ A, const __half* __restrict__ B,
    const float* __restrict__ bias, void* __restrict__ Cv,
    int K, int lda, int ldb, int ldc)
{
    extern __shared__ char sm[];
    const uint32_t sbase = smem_u32(sm);
    const int tid = threadIdx.x;
    const int lane = tid & 31, wid = tid >> 5;
    const int wm = wid >> 2, wn = wid & 3;        // 2 x 4 warps, warp tile 64x32
    const int bm = blockIdx.y * CTA_M;
    const int bn = blockIdx.x * CTA_N;

    const int lrow = tid >> 3;      // 0..31
    const int lc = tid & 7;

    auto load_stage = [&](int s, int k0) {
        uint32_t sa = sbase + s * STAGE_BYTES;
        uint32_t sb = sa + A_BYTES;
        const __half* gA = A + (size_t)bm * lda + k0 + lc * 8;
        const __half* gB = B + (size_t)bn * ldb + k0 + lc * 8;
        #pragma unroll
        for (int j = 0; j < 4; j++) {
            int r = lrow + 32 * j;
            cp16(tile_addr(sa, r, lc), gA + (size_t)r * lda);
        }
        #pragma unroll
        for (int j = 0; j < 4; j++) {
            int r = lrow + 32 * j;
            cp16(tile_addr(sb, r, lc), gB + (size_t)r * ldb);
        }
    };

    float acc[4][4][4];
    #pragma unroll
    for (int i = 0; i < 4; i++)
        #pragma unroll
        for (int j = 0; j < 4; j++)
            #pragma unroll
            for (int r = 0; r < 4; r++)
                acc[i][j][r] = 0.0f;

    const int T = K / CTA_K;
    load_stage(0, 0);
    cp_commit();
    load_stage(1, CTA_K);
    cp_commit();

    for (int it = 0; it < T; ++it) {
        cp_wait<1>();
        __syncthreads();
        if (it + 2 < T) load_stage((it + 2) % NSTAGES, (it + 2) * CTA_K);
        cp_commit();

        const int s = it % NSTAGES;
        const uint32_t sa = sbase + s * STAGE_BYTES;
        const uint32_t sb = sa + A_BYTES;

        #pragma unroll
        for (int kt = 0; kt < 4; kt++) {
            uint32_t af[4][4];
            uint32_t bf[2][4];
            #pragma unroll
            for (int mt = 0; mt < 4; mt++)
                ldsm4(af[mt], frag_addr(sa, wm * 64 + mt * 16, kt, lane));
            #pragma unroll
            for (int ng = 0; ng < 2; ng++)
                ldsm4(bf[ng], frag_addr(sb, wn * 32 + ng * 16, kt, lane));
            #pragma unroll
            for (int mt = 0; mt < 4; mt++) {
                #pragma unroll
                for (int ng = 0; ng < 2; ng++) {
                    mma_f16(acc[mt][2 * ng],     af[mt], bf[ng][0], bf[ng][2]);
                    mma_f16(acc[mt][2 * ng + 1], af[mt], bf[ng][1], bf[ng][3]);
                }
            }
        }
    }

    // ---- epilogue ----
    const int g = lane >> 2, tig = lane & 3;
    #pragma unroll
    for (int mt = 0; mt < 4; mt++) {
        #pragma unroll
        for (int nt = 0; nt < 4; nt++) {
            int row = bm + wm * 64 + mt * 16 + g;
            int col = bn + wn * 32 + nt * 8 + tig * 2;
            if (EPI_HALF) {
                __half* C = (__half*)Cv;
                *reinterpret_cast<uint32_t*>(C + (size_t)row * ldc + col) =
                    h2pack(acc[mt][nt][0], acc[mt][nt][1]);
                *reinterpret_cast<uint32_t*>(C + (size_t)(row + 8) * ldc + col) =
                    h2pack(acc[mt][nt][2], acc[mt][nt][3]);
            } else {
                float* C = (float*)Cv;
                float2 b = *reinterpret_cast<const float2*>(bias + col);
                *reinterpret_cast<float2*>(C + (size_t)row * ldc + col) =
                    make_float2(acc[mt][nt][0] + b.x, acc[mt][nt][1] + b.y);
                *reinterpret_cast<float2*>(C + (size_t)(row + 8) * ldc + col) =
                    make_float2(acc[mt][nt][2] + b.x, acc[mt][nt][3] + b.y);
            }
        }
    }
}

extern "C" void kernel_launch(void* const* d_in, const int* in_sizes, int n_in,
                              void* d_out, int out_size)
{
    const float* x    = (const float*)d_in[0];   // [8192,4096]
    const float* U    = (const float*)d_in[1];   // [4096,1024]
    const float* S    = (const float*)d_in[2];   // [1024]
    const float* V    = (const float*)d_in[3];   // [4096,1024]
    const float* bias = (const float*)d_in[4];   // [4096]
    float* out = (float*)d_out;                  // [8192,4096]

    __half *xh, *Vth, *Uh, *Ts;
    cudaGetSymbolAddress((void**)&xh, g_xh);
    cudaGetSymbolAddress((void**)&Vth, g_Vth);
    cudaGetSymbolAddress((void**)&Uh, g_Uh);
    cudaGetSymbolAddress((void**)&Ts, g_Ts);

    cudaFuncSetAttribute(hgemm_async<true>,
                         cudaFuncAttributeMaxDynamicSharedMemorySize, SMEM_TOTAL);
    cudaFuncSetAttribute(hgemm_async<false>,
                         cudaFuncAttributeMaxDynamicSharedMemorySize, SMEM_TOTAL);

    // prep
    cvt_f2h<<<(8192 * 4096 / 4) / 256, 256>>>(x, xh);
    cvt_f2h<<<(4096 * 1024 / 4) / 256, 256>>>(U, Uh);
    prep_vt_h<<<dim3(128, 32), dim3(32, 8)>>>(V, S, Vth);

    // GEMM1: Ts = xh @ Vth^T   (M=8192,N=1024,K=4096)
    hgemm_async<true><<<dim3(1024 / CTA_N, 8192 / CTA_M), 256, SMEM_TOTAL>>>(
        xh, Vth, nullptr, Ts, 4096, 4096, 4096, 1024);

    // GEMM2: out = Ts @ Uh^T + bias   (M=8192,N=4096,K=1024)
    hgemm_async<false><<<dim3(4096 / CTA_N, 8192 / CTA_M), 256, SMEM_TOTAL>>>(
        Ts, Uh, bias, out, 1024, 1024, 1024, 4096);
}